// round 11
// baseline (speedup 1.0000x reference)
#include <cuda_runtime.h>
#include <cstdint>

#define EPS_F 1e-9f
#define DIM   128
#define NTHR  256
#define EBLK  1184
#define NBUILD 592              // builder blocks; <= guaranteed wave-1 residency (5/SM*148=740)
#define MAX_NODES 200000

// Scratch (no allocations allowed)
__device__ float2       g_tab[MAX_NODES];
__device__ double       g_part_prox[EBLK];
__device__ double       g_part_comp[NBUILD];
__device__ unsigned int g_built = 0;   // build-phase release counter
__device__ unsigned int g_done  = 0;   // completion ticket

// ---------------------------------------------------------------------------
__device__ __forceinline__ double block_reduce_double(double v, double* s) {
    int lane = threadIdx.x & 31;
    int wid  = threadIdx.x >> 5;
    #pragma unroll
    for (int o = 16; o; o >>= 1) v += __shfl_down_sync(0xffffffffu, v, o);
    if (lane == 0) s[wid] = v;
    __syncthreads();
    v = (threadIdx.x < (NTHR >> 5)) ? s[threadIdx.x] : 0.0;
    if (wid == 0) {
        #pragma unroll
        for (int o = 16; o; o >>= 1) v += __shfl_down_sync(0xffffffffu, v, o);
    }
    return v;  // valid on thread 0
}

// Exact fp32 rounding-order replication of the reference (no FMA contraction).
__device__ __forceinline__ float ref_inner(float ax, float ay, float bx, float by) {
    float u = __fadd_rn(__fmul_rn(ax, bx), __fmul_rn(ay, by));
    return __fadd_rn(-u, 1.0f);
}

__device__ __forceinline__ float ref_safe_div(float num, float den) {
    float sgn  = (den > 0.0f) ? 1.0f : ((den < 0.0f) ? -1.0f : 0.0f);
    float safe = __fmul_rn(fmaxf(fabsf(den), EPS_F), sgn);
    return __fdiv_rn(num, safe);
}

__device__ __forceinline__ float edge_quad(float2 a, float2 b) {
    float aa  = ref_inner(a.x, a.y, a.x, a.y);
    float bb  = ref_inner(b.x, b.y, b.x, b.y);
    float ab  = ref_inner(a.x, a.y, b.x, b.y);
    float den = __fmul_rn(aa, bb);
    float num = __fsub_rn(__fmul_rn(ab, ab), den);
    return ref_safe_div(num, den);
}

// ---------------------------------------------------------------------------
// Single kernel: builder blocks fill the table (+compactness), everyone spins
// on the release flag, then the R3-shaped edge loop, then ticket finish.
__global__ __launch_bounds__(NTHR, 5)
void fused_kernel(const float* __restrict__ z,
                  const int*  __restrict__ src,
                  const int*  __restrict__ dst,
                  long long n_edges, int n_nodes,
                  float* __restrict__ out) {
    __shared__ double s_red[32];
    __shared__ double s_pc[2];
    __shared__ unsigned int s_last;

    // ---- phase 1: builders fill table + compactness partial ---------------
    if (blockIdx.x < NBUILD) {
        int per_blk = (n_nodes + NBUILD - 1) / NBUILD;
        int lo = blockIdx.x * per_blk;
        int hi = min(lo + per_blk, n_nodes);
        double comp = 0.0;
        for (int i = lo + threadIdx.x; i < hi; i += NTHR) {
            float2 xy = *reinterpret_cast<const float2*>(z + (size_t)i * DIM);
            g_tab[i] = xy;
            float aa  = ref_inner(xy.x, xy.y, xy.x, xy.y);
            float num = __fsub_rn(1.0f, aa);   // ab*ab - aa*bb, ab=bb=1
            comp += (double)ref_safe_div(num, aa);
        }
        double bc = block_reduce_double(comp, s_red);
        __syncthreads();
        if (threadIdx.x == 0) {
            g_part_comp[blockIdx.x] = bc;
            __threadfence();                 // release table + partial
            atomicAdd(&g_built, 1u);
        }
    }

    // ---- spin until all builder slices are published ----------------------
    if (threadIdx.x == 0) {
        while (atomicAdd(&g_built, 0u) < (unsigned int)NBUILD) { __nanosleep(64); }
    }
    __syncthreads();
    __threadfence();                         // acquire

    // ---- phase 2: proximity over all edges (R3 config) --------------------
    long long tid    = (long long)blockIdx.x * NTHR + threadIdx.x;
    long long stride = (long long)EBLK * NTHR;

    double prox = 0.0;
    long long n4 = n_edges >> 2;
    const int4* s4 = reinterpret_cast<const int4*>(src);
    const int4* d4 = reinterpret_cast<const int4*>(dst);
    #pragma unroll 1
    for (long long i = tid; i < n4; i += stride) {
        int4 s = s4[i];
        int4 d = d4[i];
        float2 a0 = g_tab[s.x], b0 = g_tab[d.x];
        float2 a1 = g_tab[s.y], b1 = g_tab[d.y];
        float2 a2 = g_tab[s.z], b2 = g_tab[d.z];
        float2 a3 = g_tab[s.w], b3 = g_tab[d.w];
        float q0 = edge_quad(a0, b0);
        float q1 = edge_quad(a1, b1);
        float q2 = edge_quad(a2, b2);
        float q3 = edge_quad(a3, b3);
        prox += (double)__fadd_rn(__fadd_rn(q0, q1), __fadd_rn(q2, q3));
    }
    for (long long e = (n4 << 2) + tid; e < n_edges; e += stride) {
        prox += (double)edge_quad(g_tab[src[e]], g_tab[dst[e]]);
    }

    double bp = block_reduce_double(prox, s_red);
    if (threadIdx.x == 0) {
        g_part_prox[blockIdx.x] = bp;
        __threadfence();
        unsigned int t = atomicAdd(&g_done, 1u);
        s_last = (t == EBLK - 1) ? 1u : 0u;
    }
    __syncthreads();

    // ---- phase 3: last block finishes -------------------------------------
    if (s_last) {
        double p = 0.0, c = 0.0;
        for (int i = threadIdx.x; i < EBLK; i += NTHR) p += g_part_prox[i];
        for (int i = threadIdx.x; i < NBUILD; i += NTHR) c += g_part_comp[i];
        p = block_reduce_double(p, s_red);
        __syncthreads();
        c = block_reduce_double(c, s_red);
        if (threadIdx.x == 0) { s_pc[0] = p; s_pc[1] = c; }
        __syncthreads();

        if (threadIdx.x < 32) {
            int n_sp = (int)((n_edges < 10) ? n_edges : 10);
            double q = 0.0;
            if (threadIdx.x < n_sp) {
                float2 a = g_tab[src[threadIdx.x]];
                float2 b = g_tab[dst[threadIdx.x]];
                // lines: cross([x,y,1],[0,0,1]) = (y, -x, 0); time = 0
                float aa  = -__fadd_rn(__fmul_rn(a.y, a.y), __fmul_rn(a.x, a.x));
                float bb  = -__fadd_rn(__fmul_rn(b.y, b.y), __fmul_rn(b.x, b.x));
                float ab  = -__fadd_rn(__fmul_rn(a.y, b.y), __fmul_rn(a.x, b.x));
                float den = __fmul_rn(aa, bb);
                float num = __fsub_rn(__fmul_rn(ab, ab), den);
                q = (double)ref_safe_div(num, den);
            }
            #pragma unroll
            for (int o = 16; o; o >>= 1) q += __shfl_down_sync(0xffffffffu, q, o);
            if (threadIdx.x == 0) {
                double prox_m = s_pc[0] / (double)n_edges;
                double comp_m = s_pc[1] / (double)n_nodes;
                double spr_m  = q / (double)n_sp;
                out[0] = (float)((prox_m + comp_m) + 0.1 * spr_m);
                g_done  = 0u;   // reset for next graph replay (all blocks past
                g_built = 0u;   // the spin once every ticket has arrived)
            }
        }
    }
}

// ---------------------------------------------------------------------------
extern "C" void kernel_launch(void* const* d_in, const int* in_sizes, int n_in,
                              void* d_out, int out_size) {
    const float* z  = (const float*)d_in[0];
    const int*   ei = (const int*)d_in[1];

    int       n_nodes = in_sizes[0] / DIM;
    long long n_edges = (long long)in_sizes[1] / 2;
    const int* src = ei;
    const int* dst = ei + n_edges;

    fused_kernel<<<EBLK, NTHR>>>(z, src, dst, n_edges, n_nodes, (float*)d_out);
}

// round 12
// speedup vs baseline: 1.0215x; 1.0215x over previous
#include <cuda_runtime.h>
#include <cstdint>

#define EPS_F 1e-9f
#define DIM   128
#define NTHR  256
#define EBLK  1184
#define NBA_MAX 1024
#define MAX_NODES 200000

// Scratch (no allocations allowed)
__device__ float2       g_tab[MAX_NODES];
__device__ double       g_part_prox[EBLK];
__device__ double       g_part_comp[NBA_MAX];
__device__ unsigned int g_done = 0;

// ---------------------------------------------------------------------------
__device__ __forceinline__ double block_reduce_double(double v, double* s) {
    int lane = threadIdx.x & 31;
    int wid  = threadIdx.x >> 5;
    #pragma unroll
    for (int o = 16; o; o >>= 1) v += __shfl_down_sync(0xffffffffu, v, o);
    if (lane == 0) s[wid] = v;
    __syncthreads();
    v = (threadIdx.x < (NTHR >> 5)) ? s[threadIdx.x] : 0.0;
    if (wid == 0) {
        #pragma unroll
        for (int o = 16; o; o >>= 1) v += __shfl_down_sync(0xffffffffu, v, o);
    }
    return v;  // valid on thread 0
}

// Exact fp32 rounding-order replication of the reference (no FMA contraction).
__device__ __forceinline__ float ref_inner(float ax, float ay, float bx, float by) {
    float u = __fadd_rn(__fmul_rn(ax, bx), __fmul_rn(ay, by));
    return __fadd_rn(-u, 1.0f);
}

__device__ __forceinline__ float ref_safe_div(float num, float den) {
    float sgn  = (den > 0.0f) ? 1.0f : ((den < 0.0f) ? -1.0f : 0.0f);
    float safe = __fmul_rn(fmaxf(fabsf(den), EPS_F), sgn);
    return __fdiv_rn(num, safe);
}

__device__ __forceinline__ float edge_quad(float2 a, float2 b) {
    float aa  = ref_inner(a.x, a.y, a.x, a.y);
    float bb  = ref_inner(b.x, b.y, b.x, b.y);
    float ab  = ref_inner(a.x, a.y, b.x, b.y);
    float den = __fmul_rn(aa, bb);
    float num = __fsub_rn(__fmul_rn(ab, ab), den);
    return ref_safe_div(num, den);
}

__device__ __forceinline__ float quad4(int4 s, int4 d) {
    float2 a0 = g_tab[s.x], b0 = g_tab[d.x];
    float2 a1 = g_tab[s.y], b1 = g_tab[d.y];
    float2 a2 = g_tab[s.z], b2 = g_tab[d.z];
    float2 a3 = g_tab[s.w], b3 = g_tab[d.w];
    float q0 = edge_quad(a0, b0);
    float q1 = edge_quad(a1, b1);
    float q2 = edge_quad(a2, b2);
    float q3 = edge_quad(a3, b3);
    return __fadd_rn(__fadd_rn(q0, q1), __fadd_rn(q2, q3));
}

// ---------------------------------------------------------------------------
// Kernel A: build compact (x,y) table + per-block compactness partials.
__global__ __launch_bounds__(NTHR)
void node_kernel(const float* __restrict__ z, int n_nodes) {
    __shared__ double s_red[32];
    int i = blockIdx.x * NTHR + threadIdx.x;
    double comp = 0.0;
    if (i < n_nodes) {
        float2 xy = *reinterpret_cast<const float2*>(z + (size_t)i * DIM);
        g_tab[i] = xy;
        float aa  = ref_inner(xy.x, xy.y, xy.x, xy.y);
        float num = __fsub_rn(1.0f, aa);   // ab*ab - aa*bb with ab=bb=1
        comp = (double)ref_safe_div(num, aa);
    }
    double bsum = block_reduce_double(comp, s_red);
    if (threadIdx.x == 0) g_part_comp[blockIdx.x] = bsum;
}

// ---------------------------------------------------------------------------
// Kernel B: proximity over edges. PDL: prefetch first indices before the
// dependency sync; peeled first iteration keeps the hot loop branch-free.
__global__ __launch_bounds__(NTHR)
void edge_kernel(const int* __restrict__ src,
                 const int* __restrict__ dst,
                 long long n_edges, int n_nodes, int n_comp_blocks,
                 float* __restrict__ out) {
    __shared__ double s_red[32];
    __shared__ double s_pc[2];
    __shared__ unsigned int s_last;

    long long tid    = (long long)blockIdx.x * NTHR + threadIdx.x;
    long long stride = (long long)gridDim.x * NTHR;

    long long n4 = n_edges >> 2;
    const int4* s4 = reinterpret_cast<const int4*>(src);
    const int4* d4 = reinterpret_cast<const int4*>(dst);

    // Prefetch this thread's first indices while node_kernel drains.
    int4 s_pre = make_int4(0, 0, 0, 0), d_pre = make_int4(0, 0, 0, 0);
    bool has_pre = (tid < n4);
    if (has_pre) {
        s_pre = s4[tid];
        d_pre = d4[tid];
    }

    // Wait for node_kernel completion (table writes flushed & visible).
    cudaGridDependencySynchronize();

    double prox = 0.0;
    // peeled first iteration (uses prefetched indices)
    if (has_pre) prox += (double)quad4(s_pre, d_pre);
    // branch-free steady state, identical to the fastest-measured R3 body
    #pragma unroll 1
    for (long long i = tid + stride; i < n4; i += stride) {
        prox += (double)quad4(s4[i], d4[i]);
    }
    for (long long e = (n4 << 2) + tid; e < n_edges; e += stride) {
        prox += (double)edge_quad(g_tab[src[e]], g_tab[dst[e]]);
    }

    double bp = block_reduce_double(prox, s_red);
    if (threadIdx.x == 0) {
        g_part_prox[blockIdx.x] = bp;
        __threadfence();
        unsigned int t = atomicAdd(&g_done, 1u);
        s_last = (t == gridDim.x - 1) ? 1u : 0u;
    }
    __syncthreads();

    if (s_last) {
        double p = 0.0, c = 0.0;
        for (int i = threadIdx.x; i < gridDim.x; i += NTHR) p += g_part_prox[i];
        for (int i = threadIdx.x; i < n_comp_blocks; i += NTHR) c += g_part_comp[i];
        p = block_reduce_double(p, s_red);
        __syncthreads();
        c = block_reduce_double(c, s_red);
        if (threadIdx.x == 0) { s_pc[0] = p; s_pc[1] = c; }
        __syncthreads();

        if (threadIdx.x < 32) {
            int n_sp = (int)((n_edges < 10) ? n_edges : 10);
            double q = 0.0;
            if (threadIdx.x < n_sp) {
                float2 a = g_tab[src[threadIdx.x]];
                float2 b = g_tab[dst[threadIdx.x]];
                // lines: cross([x,y,1],[0,0,1]) = (y, -x, 0); time = 0
                float aa  = -__fadd_rn(__fmul_rn(a.y, a.y), __fmul_rn(a.x, a.x));
                float bb  = -__fadd_rn(__fmul_rn(b.y, b.y), __fmul_rn(b.x, b.x));
                float ab  = -__fadd_rn(__fmul_rn(a.y, b.y), __fmul_rn(a.x, b.x));
                float den = __fmul_rn(aa, bb);
                float num = __fsub_rn(__fmul_rn(ab, ab), den);
                q = (double)ref_safe_div(num, den);
            }
            #pragma unroll
            for (int o = 16; o; o >>= 1) q += __shfl_down_sync(0xffffffffu, q, o);
            if (threadIdx.x == 0) {
                double prox_m = s_pc[0] / (double)n_edges;
                double comp_m = s_pc[1] / (double)n_nodes;
                double spr_m  = q / (double)n_sp;
                out[0] = (float)((prox_m + comp_m) + 0.1 * spr_m);
                g_done = 0u;   // reset for next graph replay
            }
        }
    }
}

// ---------------------------------------------------------------------------
extern "C" void kernel_launch(void* const* d_in, const int* in_sizes, int n_in,
                              void* d_out, int out_size) {
    const float* z  = (const float*)d_in[0];
    const int*   ei = (const int*)d_in[1];

    int       n_nodes = in_sizes[0] / DIM;
    long long n_edges = (long long)in_sizes[1] / 2;
    const int* src = ei;
    const int* dst = ei + n_edges;

    int nba = (n_nodes + NTHR - 1) / NTHR;
    node_kernel<<<nba, NTHR>>>(z, n_nodes);

    // Edge kernel with programmatic dependent launch.
    cudaLaunchConfig_t cfg = {};
    cfg.gridDim  = dim3(EBLK, 1, 1);
    cfg.blockDim = dim3(NTHR, 1, 1);
    cfg.dynamicSmemBytes = 0;
    cfg.stream = 0;
    cudaLaunchAttribute attr[1];
    attr[0].id = cudaLaunchAttributeProgrammaticStreamSerialization;
    attr[0].val.programmaticStreamSerializationAllowed = 1;
    cfg.attrs = attr;
    cfg.numAttrs = 1;
    cudaLaunchKernelEx(&cfg, edge_kernel, src, dst, n_edges, n_nodes, nba,
                       (float*)d_out);
}

// round 13
// speedup vs baseline: 1.0596x; 1.0372x over previous
#include <cuda_runtime.h>
#include <cstdint>

#define EPS_F 1e-9f
#define DIM   128
#define NTHR  256
#define EBLK  1184
#define NBA_MAX 1024
#define MAX_NODES 200000

// Scratch (no allocations allowed)
__device__ float2       g_tab[MAX_NODES];
__device__ double       g_part_prox[EBLK];
__device__ double       g_part_comp[NBA_MAX];
__device__ unsigned int g_done = 0;

// ---------------------------------------------------------------------------
__device__ __forceinline__ double block_reduce_double(double v, double* s) {
    int lane = threadIdx.x & 31;
    int wid  = threadIdx.x >> 5;
    #pragma unroll
    for (int o = 16; o; o >>= 1) v += __shfl_down_sync(0xffffffffu, v, o);
    if (lane == 0) s[wid] = v;
    __syncthreads();
    v = (threadIdx.x < (NTHR >> 5)) ? s[threadIdx.x] : 0.0;
    if (wid == 0) {
        #pragma unroll
        for (int o = 16; o; o >>= 1) v += __shfl_down_sync(0xffffffffu, v, o);
    }
    return v;  // valid on thread 0
}

// Exact fp32 rounding-order replication of the reference (no FMA contraction).
__device__ __forceinline__ float ref_inner(float ax, float ay, float bx, float by) {
    float u = __fadd_rn(__fmul_rn(ax, bx), __fmul_rn(ay, by));
    return __fadd_rn(-u, 1.0f);
}

__device__ __forceinline__ float ref_safe_div(float num, float den) {
    float sgn  = (den > 0.0f) ? 1.0f : ((den < 0.0f) ? -1.0f : 0.0f);
    float safe = __fmul_rn(fmaxf(fabsf(den), EPS_F), sgn);
    return __fdiv_rn(num, safe);
}

__device__ __forceinline__ float edge_quad(float2 a, float2 b) {
    float aa  = ref_inner(a.x, a.y, a.x, a.y);
    float bb  = ref_inner(b.x, b.y, b.x, b.y);
    float ab  = ref_inner(a.x, a.y, b.x, b.y);
    float den = __fmul_rn(aa, bb);
    float num = __fsub_rn(__fmul_rn(ab, ab), den);
    return ref_safe_div(num, den);
}

// ---------------------------------------------------------------------------
// Kernel A: build compact (x,y) table + per-block compactness partials.
__global__ __launch_bounds__(NTHR)
void node_kernel(const float* __restrict__ z, int n_nodes) {
    __shared__ double s_red[32];
    int i = blockIdx.x * NTHR + threadIdx.x;
    double comp = 0.0;
    if (i < n_nodes) {
        float2 xy = *reinterpret_cast<const float2*>(z + (size_t)i * DIM);
        g_tab[i] = xy;
        float aa  = ref_inner(xy.x, xy.y, xy.x, xy.y);
        float num = __fsub_rn(1.0f, aa);   // ab*ab - aa*bb with ab=bb=1
        comp = (double)ref_safe_div(num, aa);
    }
    double bsum = block_reduce_double(comp, s_red);
    if (threadIdx.x == 0) g_part_comp[blockIdx.x] = bsum;
}

// ---------------------------------------------------------------------------
// Kernel B: proximity over edges (best-measured config). Launched with PDL so
// its setup and first index prefetch overlap node_kernel's tail.
__global__ __launch_bounds__(NTHR)
void edge_kernel(const int* __restrict__ src,
                 const int* __restrict__ dst,
                 long long n_edges, int n_nodes, int n_comp_blocks,
                 float* __restrict__ out) {
    __shared__ double s_red[32];
    __shared__ double s_pc[2];
    __shared__ unsigned int s_last;

    long long tid    = (long long)blockIdx.x * NTHR + threadIdx.x;
    long long stride = (long long)gridDim.x * NTHR;

    long long n4 = n_edges >> 2;
    const int4* s4 = reinterpret_cast<const int4*>(src);
    const int4* d4 = reinterpret_cast<const int4*>(dst);

    // Prefetch this thread's first indices while the node kernel drains.
    int4 s_pre = make_int4(0, 0, 0, 0), d_pre = make_int4(0, 0, 0, 0);
    bool has_pre = (tid < n4);
    if (has_pre) {
        s_pre = __ldcs(s4 + tid);
        d_pre = __ldcs(d4 + tid);
    }

    // Wait for node_kernel completion (table writes flushed & visible).
    cudaGridDependencySynchronize();

    double prox = 0.0;
    for (long long i = tid; i < n4; i += stride) {
        int4 s, d;
        if (i == tid && has_pre) { s = s_pre; d = d_pre; }
        else { s = __ldcs(s4 + i); d = __ldcs(d4 + i); }
        float2 a0 = g_tab[s.x], b0 = g_tab[d.x];
        float2 a1 = g_tab[s.y], b1 = g_tab[d.y];
        float2 a2 = g_tab[s.z], b2 = g_tab[d.z];
        float2 a3 = g_tab[s.w], b3 = g_tab[d.w];
        float q0 = edge_quad(a0, b0);
        float q1 = edge_quad(a1, b1);
        float q2 = edge_quad(a2, b2);
        float q3 = edge_quad(a3, b3);
        prox += (double)__fadd_rn(__fadd_rn(q0, q1), __fadd_rn(q2, q3));
    }
    for (long long e = (n4 << 2) + tid; e < n_edges; e += stride) {
        prox += (double)edge_quad(g_tab[src[e]], g_tab[dst[e]]);
    }

    double bp = block_reduce_double(prox, s_red);
    if (threadIdx.x == 0) {
        g_part_prox[blockIdx.x] = bp;
        __threadfence();
        unsigned int t = atomicAdd(&g_done, 1u);
        s_last = (t == gridDim.x - 1) ? 1u : 0u;
    }
    __syncthreads();

    if (s_last) {
        double p = 0.0, c = 0.0;
        for (int i = threadIdx.x; i < gridDim.x; i += NTHR) p += g_part_prox[i];
        for (int i = threadIdx.x; i < n_comp_blocks; i += NTHR) c += g_part_comp[i];
        p = block_reduce_double(p, s_red);
        __syncthreads();
        c = block_reduce_double(c, s_red);
        if (threadIdx.x == 0) { s_pc[0] = p; s_pc[1] = c; }
        __syncthreads();

        if (threadIdx.x < 32) {
            int n_sp = (int)((n_edges < 10) ? n_edges : 10);
            double q = 0.0;
            if (threadIdx.x < n_sp) {
                float2 a = g_tab[src[threadIdx.x]];
                float2 b = g_tab[dst[threadIdx.x]];
                // lines: cross([x,y,1],[0,0,1]) = (y, -x, 0); time = 0
                float aa  = -__fadd_rn(__fmul_rn(a.y, a.y), __fmul_rn(a.x, a.x));
                float bb  = -__fadd_rn(__fmul_rn(b.y, b.y), __fmul_rn(b.x, b.x));
                float ab  = -__fadd_rn(__fmul_rn(a.y, b.y), __fmul_rn(a.x, b.x));
                float den = __fmul_rn(aa, bb);
                float num = __fsub_rn(__fmul_rn(ab, ab), den);
                q = (double)ref_safe_div(num, den);
            }
            #pragma unroll
            for (int o = 16; o; o >>= 1) q += __shfl_down_sync(0xffffffffu, q, o);
            if (threadIdx.x == 0) {
                double prox_m = s_pc[0] / (double)n_edges;
                double comp_m = s_pc[1] / (double)n_nodes;
                double spr_m  = q / (double)n_sp;
                out[0] = (float)((prox_m + comp_m) + 0.1 * spr_m);
                g_done = 0u;   // reset for next graph replay
            }
        }
    }
}

// ---------------------------------------------------------------------------
extern "C" void kernel_launch(void* const* d_in, const int* in_sizes, int n_in,
                              void* d_out, int out_size) {
    const float* z  = (const float*)d_in[0];
    const int*   ei = (const int*)d_in[1];

    int       n_nodes = in_sizes[0] / DIM;
    long long n_edges = (long long)in_sizes[1] / 2;
    const int* src = ei;
    const int* dst = ei + n_edges;

    int nba = (n_nodes + NTHR - 1) / NTHR;
    node_kernel<<<nba, NTHR>>>(z, n_nodes);

    // Edge kernel with programmatic dependent launch: overlaps its setup with
    // node_kernel's tail; cudaGridDependencySynchronize() inside the kernel
    // enforces the table dependency.
    cudaLaunchConfig_t cfg = {};
    cfg.gridDim  = dim3(EBLK, 1, 1);
    cfg.blockDim = dim3(NTHR, 1, 1);
    cfg.dynamicSmemBytes = 0;
    cfg.stream = 0;
    cudaLaunchAttribute attr[1];
    attr[0].id = cudaLaunchAttributeProgrammaticStreamSerialization;
    attr[0].val.programmaticStreamSerializationAllowed = 1;
    cfg.attrs = attr;
    cfg.numAttrs = 1;
    cudaLaunchKernelEx(&cfg, edge_kernel, src, dst, n_edges, n_nodes, nba,
                       (float*)d_out);
}